// round 2
// baseline (speedup 1.0000x reference)
#include <cuda_runtime.h>

// ChannelSelfAttention: B=4,H=512,W=256, C=2.
// One block per (b,h) row; thread w = query position.
// Unnormalized softmax (no max pass): scores are O(10), exp2 safe in fp32.

#define W 256

__device__ __forceinline__ float fast_exp2(float x) {
    float r;
    asm("ex2.approx.f32 %0, %1;" : "=f"(r) : "f"(x));  // MUFU.EX2
    return r;
}

__global__ __launch_bounds__(W) void channel_attn_kernel(
    const float* __restrict__ x1, const float* __restrict__ x2,
    const float* __restrict__ wq, const float* __restrict__ bq,
    const float* __restrict__ wk, const float* __restrict__ bk,
    const float* __restrict__ wv, const float* __restrict__ bv,
    float* __restrict__ out1, float* __restrict__ out2)
{
    __shared__ float4 kv[W];  // {k0, k1, v0, v1} per key position

    const int row = blockIdx.x;          // b*H + h
    const int w   = threadIdx.x;
    const int idx = row * W + w;

    const float a = x1[idx];
    const float b = x2[idx];

    // 1x1 conv projections (channel matmul 2x2 + bias)
    float q0 = fmaf(wq[0], a, fmaf(wq[1], b, bq[0]));
    float q1 = fmaf(wq[2], a, fmaf(wq[3], b, bq[1]));
    const float k0 = fmaf(wk[0], a, fmaf(wk[1], b, bk[0]));
    const float k1 = fmaf(wk[2], a, fmaf(wk[3], b, bk[1]));
    const float v0 = fmaf(wv[0], a, fmaf(wv[1], b, bv[0]));
    const float v1 = fmaf(wv[2], a, fmaf(wv[3], b, bv[1]));

    kv[w] = make_float4(k0, k1, v0, v1);

    // Pre-fold log2(e) into q so the inner loop uses raw EX2.
    const float LOG2E = 1.4426950408889634f;
    q0 *= LOG2E;
    q1 *= LOG2E;

    __syncthreads();

    float sum = 0.f, acc0 = 0.f, acc1 = 0.f;

#pragma unroll 8
    for (int u = 0; u < W; ++u) {
        const float4 t = kv[u];                 // LDS.128 broadcast
        const float s = fmaf(q0, t.x, q1 * t.y);
        const float e = fast_exp2(s);           // MUFU.EX2
        sum  += e;
        acc0 = fmaf(e, t.z, acc0);
        acc1 = fmaf(e, t.w, acc1);
    }

    const float inv = 1.0f / sum;
    out1[idx] = fmaf(acc0, inv, a);
    out2[idx] = fmaf(acc1, inv, b);
}

extern "C" void kernel_launch(void* const* d_in, const int* in_sizes, int n_in,
                              void* d_out, int out_size)
{
    const float* x1 = (const float*)d_in[0];
    const float* x2 = (const float*)d_in[1];
    const float* wq = (const float*)d_in[2];
    const float* bq = (const float*)d_in[3];
    const float* wk = (const float*)d_in[4];
    const float* bk = (const float*)d_in[5];
    const float* wv = (const float*)d_in[6];
    const float* bv = (const float*)d_in[7];

    float* out = (float*)d_out;
    const int N = in_sizes[0];        // B*H*W = 524288
    const int rows = N / W;           // 2048

    channel_attn_kernel<<<rows, W>>>(x1, x2, wq, bq, wk, bk, wv, bv,
                                     out, out + N);
}

// round 3
// speedup vs baseline: 1.0553x; 1.0553x over previous
#include <cuda_runtime.h>

// ChannelSelfAttention: B=4,H=512,W=256, C=2.
// One block per (b,h) row; thread w = query position.
// Packed f32x2 math over key pairs (even/odd lanes of 64-bit register pairs).
// Unnormalized softmax (no max pass): scores are O(10), exp2 safe in fp32.

#define W 256

__device__ __forceinline__ float fast_exp2(float x) {
    float r;
    asm("ex2.approx.f32 %0, %1;" : "=f"(r) : "f"(x));  // MUFU.EX2
    return r;
}

__global__ __launch_bounds__(W) void channel_attn_kernel(
    const float* __restrict__ x1, const float* __restrict__ x2,
    const float* __restrict__ wq, const float* __restrict__ bq,
    const float* __restrict__ wk, const float* __restrict__ bk,
    const float* __restrict__ wv, const float* __restrict__ bv,
    float* __restrict__ out1, float* __restrict__ out2)
{
    // Pair-interleaved layout: kk[j] = {k0[2j], k0[2j+1], k1[2j], k1[2j+1]}
    //                          vv[j] = {v0[2j], v0[2j+1], v1[2j], v1[2j+1]}
    __shared__ float kk[W * 2];
    __shared__ float vv[W * 2];

    const int row = blockIdx.x;          // b*H + h
    const int w   = threadIdx.x;
    const int idx = row * W + w;

    const float a = x1[idx];
    const float b = x2[idx];

    // 1x1 conv projections (channel matmul 2x2 + bias)
    float q0 = fmaf(wq[0], a, fmaf(wq[1], b, bq[0]));
    float q1 = fmaf(wq[2], a, fmaf(wq[3], b, bq[1]));
    const float k0 = fmaf(wk[0], a, fmaf(wk[1], b, bk[0]));
    const float k1 = fmaf(wk[2], a, fmaf(wk[3], b, bk[1]));
    const float v0 = fmaf(wv[0], a, fmaf(wv[1], b, bv[0]));
    const float v1 = fmaf(wv[2], a, fmaf(wv[3], b, bv[1]));

    // Scatter into pair-interleaved layout.
    {
        const int base = (w >> 1) * 4 + (w & 1);
        kk[base]     = k0;
        kk[base + 2] = k1;
        vv[base]     = v0;
        vv[base + 2] = v1;
    }

    // Pre-fold log2(e) into q; broadcast each q into both lanes of a pair.
    const float LOG2E = 1.4426950408889634f;
    q0 *= LOG2E;
    q1 *= LOG2E;
    unsigned long long q0p, q1p;
    asm("mov.b64 %0, {%1,%1};" : "=l"(q0p) : "f"(q0));
    asm("mov.b64 %0, {%1,%1};" : "=l"(q1p) : "f"(q1));

    __syncthreads();

    unsigned long long sum2, acc0p, acc1p;
    {
        const float z = 0.0f;
        asm("mov.b64 %0, {%1,%1};" : "=l"(sum2)  : "f"(z));
        asm("mov.b64 %0, {%1,%1};" : "=l"(acc0p) : "f"(z));
        asm("mov.b64 %0, {%1,%1};" : "=l"(acc1p) : "f"(z));
    }

    const ulonglong2* kk2 = (const ulonglong2*)kk;
    const ulonglong2* vv2 = (const ulonglong2*)vv;

#pragma unroll 8
    for (int j = 0; j < W / 2; ++j) {
        const ulonglong2 kt = kk2[j];   // LDS.128: .x={k0e,k0o} .y={k1e,k1o}
        const ulonglong2 vt = vv2[j];   // LDS.128: .x={v0e,v0o} .y={v1e,v1o}

        unsigned long long s2;
        asm("mul.rn.f32x2 %0, %1, %2;" : "=l"(s2) : "l"(q1p), "l"(kt.y));
        asm("fma.rn.f32x2 %0, %1, %2, %3;" : "=l"(s2) : "l"(q0p), "l"(kt.x), "l"(s2));

        float se, so;
        asm("mov.b64 {%0,%1}, %2;" : "=f"(se), "=f"(so) : "l"(s2));
        const float ee = fast_exp2(se);
        const float eo = fast_exp2(so);
        unsigned long long e2;
        asm("mov.b64 %0, {%1,%2};" : "=l"(e2) : "f"(ee), "f"(eo));

        asm("add.rn.f32x2 %0, %1, %2;" : "=l"(sum2) : "l"(sum2), "l"(e2));
        asm("fma.rn.f32x2 %0, %1, %2, %3;" : "=l"(acc0p) : "l"(e2), "l"(vt.x), "l"(acc0p));
        asm("fma.rn.f32x2 %0, %1, %2, %3;" : "=l"(acc1p) : "l"(e2), "l"(vt.y), "l"(acc1p));
    }

    float s_lo, s_hi, a0_lo, a0_hi, a1_lo, a1_hi;
    asm("mov.b64 {%0,%1}, %2;" : "=f"(s_lo),  "=f"(s_hi)  : "l"(sum2));
    asm("mov.b64 {%0,%1}, %2;" : "=f"(a0_lo), "=f"(a0_hi) : "l"(acc0p));
    asm("mov.b64 {%0,%1}, %2;" : "=f"(a1_lo), "=f"(a1_hi) : "l"(acc1p));

    const float inv = 1.0f / (s_lo + s_hi);
    out1[idx] = fmaf(a0_lo + a0_hi, inv, a);
    out2[idx] = fmaf(a1_lo + a1_hi, inv, b);
}

extern "C" void kernel_launch(void* const* d_in, const int* in_sizes, int n_in,
                              void* d_out, int out_size)
{
    const float* x1 = (const float*)d_in[0];
    const float* x2 = (const float*)d_in[1];
    const float* wq = (const float*)d_in[2];
    const float* bq = (const float*)d_in[3];
    const float* wk = (const float*)d_in[4];
    const float* bk = (const float*)d_in[5];
    const float* wv = (const float*)d_in[6];
    const float* bv = (const float*)d_in[7];

    float* out = (float*)d_out;
    const int N = in_sizes[0];        // B*H*W = 524288
    const int rows = N / W;           // 2048

    channel_attn_kernel<<<rows, W>>>(x1, x2, wq, bq, wk, bk, wv, bv,
                                     out, out + N);
}

// round 8
// speedup vs baseline: 1.0561x; 1.0007x over previous
#include <cuda_runtime.h>

// ChannelSelfAttention: B=4,H=512,W=256, C=2.
// 2 rows per 256-thread block; each thread owns 2 query positions (w, w+128)
// of one row, so every kt/vt LDS.128 feeds 4 (query,key) pairs.
// Packed f32x2 math over key pairs. Unnormalized softmax (scores O(10)).

#define W 256

__device__ __forceinline__ float fast_exp2(float x) {
    float r;
    asm("ex2.approx.f32 %0, %1;" : "=f"(r) : "f"(x));  // MUFU.EX2
    return r;
}

__device__ __forceinline__ unsigned long long bcast2(float x) {
    unsigned long long p;
    asm("mov.b64 %0, {%1,%1};" : "=l"(p) : "f"(x));
    return p;
}

__global__ __launch_bounds__(256) void channel_attn_kernel(
    const float* __restrict__ x1, const float* __restrict__ x2,
    const float* __restrict__ wq, const float* __restrict__ bq,
    const float* __restrict__ wk, const float* __restrict__ bk,
    const float* __restrict__ wv, const float* __restrict__ bv,
    float* __restrict__ out1, float* __restrict__ out2)
{
    // Pair-interleaved: kk[h][(w>>1)*4 + (w&1)] = k0(w), +2 = k1(w); same for vv.
    __shared__ float kk[2][W * 2];
    __shared__ float vv[2][W * 2];

    const int t    = threadIdx.x;
    const int half = t >> 7;            // which row of the pair
    const int q    = t & 127;           // first query position
    const int row  = blockIdx.x * 2 + half;

    const int pA = q;                   // query/key position A
    const int pB = q + 128;             // query/key position B
    const int idxA = row * W + pA;
    const int idxB = row * W + pB;

    const float aA = x1[idxA], bA = x2[idxA];
    const float aB = x1[idxB], bB = x2[idxB];

    const float w00q = wq[0], w01q = wq[1], w10q = wq[2], w11q = wq[3];
    const float w00k = wk[0], w01k = wk[1], w10k = wk[2], w11k = wk[3];
    const float w00v = wv[0], w01v = wv[1], w10v = wv[2], w11v = wv[3];
    const float b0q = bq[0], b1q = bq[1];
    const float b0k = bk[0], b1k = bk[1];
    const float b0v = bv[0], b1v = bv[1];

    // Projections for both owned positions.
    float q0A = fmaf(w00q, aA, fmaf(w01q, bA, b0q));
    float q1A = fmaf(w10q, aA, fmaf(w11q, bA, b1q));
    float q0B = fmaf(w00q, aB, fmaf(w01q, bB, b0q));
    float q1B = fmaf(w10q, aB, fmaf(w11q, bB, b1q));

    {
        const float k0A = fmaf(w00k, aA, fmaf(w01k, bA, b0k));
        const float k1A = fmaf(w10k, aA, fmaf(w11k, bA, b1k));
        const float v0A = fmaf(w00v, aA, fmaf(w01v, bA, b0v));
        const float v1A = fmaf(w10v, aA, fmaf(w11v, bA, b1v));
        const int baseA = (pA >> 1) * 4 + (pA & 1);
        kk[half][baseA]     = k0A;
        kk[half][baseA + 2] = k1A;
        vv[half][baseA]     = v0A;
        vv[half][baseA + 2] = v1A;

        const float k0B = fmaf(w00k, aB, fmaf(w01k, bB, b0k));
        const float k1B = fmaf(w10k, aB, fmaf(w11k, bB, b1k));
        const float v0B = fmaf(w00v, aB, fmaf(w01v, bB, b0v));
        const float v1B = fmaf(w10v, aB, fmaf(w11v, bB, b1v));
        const int baseB = (pB >> 1) * 4 + (pB & 1);
        kk[half][baseB]     = k0B;
        kk[half][baseB + 2] = k1B;
        vv[half][baseB]     = v0B;
        vv[half][baseB + 2] = v1B;
    }

    const float LOG2E = 1.4426950408889634f;
    const unsigned long long q0pA = bcast2(q0A * LOG2E);
    const unsigned long long q1pA = bcast2(q1A * LOG2E);
    const unsigned long long q0pB = bcast2(q0B * LOG2E);
    const unsigned long long q1pB = bcast2(q1B * LOG2E);

    __syncthreads();

    unsigned long long sumA = bcast2(0.f), acc0A = bcast2(0.f), acc1A = bcast2(0.f);
    unsigned long long sumB = bcast2(0.f), acc0B = bcast2(0.f), acc1B = bcast2(0.f);

    const ulonglong2* kk2 = (const ulonglong2*)kk[half];
    const ulonglong2* vv2 = (const ulonglong2*)vv[half];

#pragma unroll 4
    for (int j = 0; j < W / 2; ++j) {
        const ulonglong2 kt = kk2[j];   // {k0e,k0o},{k1e,k1o}
        const ulonglong2 vt = vv2[j];   // {v0e,v0o},{v1e,v1o}

        // Query A
        unsigned long long sA;
        asm("mul.rn.f32x2 %0, %1, %2;" : "=l"(sA) : "l"(q1pA), "l"(kt.y));
        asm("fma.rn.f32x2 %0, %1, %2, %3;" : "=l"(sA) : "l"(q0pA), "l"(kt.x), "l"(sA));
        float seA, soA;
        asm("mov.b64 {%0,%1}, %2;" : "=f"(seA), "=f"(soA) : "l"(sA));
        const float eeA = fast_exp2(seA);
        const float eoA = fast_exp2(soA);
        unsigned long long e2A;
        asm("mov.b64 %0, {%1,%2};" : "=l"(e2A) : "f"(eeA), "f"(eoA));
        asm("add.rn.f32x2 %0, %1, %2;" : "=l"(sumA) : "l"(sumA), "l"(e2A));
        asm("fma.rn.f32x2 %0, %1, %2, %3;" : "=l"(acc0A) : "l"(e2A), "l"(vt.x), "l"(acc0A));
        asm("fma.rn.f32x2 %0, %1, %2, %3;" : "=l"(acc1A) : "l"(e2A), "l"(vt.y), "l"(acc1A));

        // Query B (same kt/vt)
        unsigned long long sB;
        asm("mul.rn.f32x2 %0, %1, %2;" : "=l"(sB) : "l"(q1pB), "l"(kt.y));
        asm("fma.rn.f32x2 %0, %1, %2, %3;" : "=l"(sB) : "l"(q0pB), "l"(kt.x), "l"(sB));
        float seB, soB;
        asm("mov.b64 {%0,%1}, %2;" : "=f"(seB), "=f"(soB) : "l"(sB));
        const float eeB = fast_exp2(seB);
        const float eoB = fast_exp2(soB);
        unsigned long long e2B;
        asm("mov.b64 %0, {%1,%2};" : "=l"(e2B) : "f"(eeB), "f"(eoB));
        asm("add.rn.f32x2 %0, %1, %2;" : "=l"(sumB) : "l"(sumB), "l"(e2B));
        asm("fma.rn.f32x2 %0, %1, %2, %3;" : "=l"(acc0B) : "l"(e2B), "l"(vt.x), "l"(acc0B));
        asm("fma.rn.f32x2 %0, %1, %2, %3;" : "=l"(acc1B) : "l"(e2B), "l"(vt.y), "l"(acc1B));
    }

    float s0, s1, a0, a1, c0, c1;

    asm("mov.b64 {%0,%1}, %2;" : "=f"(s0), "=f"(s1) : "l"(sumA));
    asm("mov.b64 {%0,%1}, %2;" : "=f"(a0), "=f"(a1) : "l"(acc0A));
    asm("mov.b64 {%0,%1}, %2;" : "=f"(c0), "=f"(c1) : "l"(acc1A));
    {
        const float inv = 1.0f / (s0 + s1);
        out1[idxA] = fmaf(a0 + a1, inv, aA);
        out2[idxA] = fmaf(c0 + c1, inv, bA);
    }

    asm("mov.b64 {%0,%1}, %2;" : "=f"(s0), "=f"(s1) : "l"(sumB));
    asm("mov.b64 {%0,%1}, %2;" : "=f"(a0), "=f"(a1) : "l"(acc0B));
    asm("mov.b64 {%0,%1}, %2;" : "=f"(c0), "=f"(c1) : "l"(acc1B));
    {
        const float inv = 1.0f / (s0 + s1);
        out1[idxB] = fmaf(a0 + a1, inv, aB);
        out2[idxB] = fmaf(c0 + c1, inv, bB);
    }
}

extern "C" void kernel_launch(void* const* d_in, const int* in_sizes, int n_in,
                              void* d_out, int out_size)
{
    const float* x1 = (const float*)d_in[0];
    const float* x2 = (const float*)d_in[1];
    const float* wq = (const float*)d_in[2];
    const float* bq = (const float*)d_in[3];
    const float* wk = (const float*)d_in[4];
    const float* bk = (const float*)d_in[5];
    const float* wv = (const float*)d_in[6];
    const float* bv = (const float*)d_in[7];

    float* out = (float*)d_out;
    const int N = in_sizes[0];        // B*H*W = 524288
    const int rows = N / W;           // 2048

    channel_attn_kernel<<<rows / 2, 256>>>(x1, x2, wq, bq, wk, bk, wv, bv,
                                           out, out + N);
}